// round 1
// baseline (speedup 1.0000x reference)
#include <cuda_runtime.h>
#include <cstdint>

#define BB   16
#define HH   512
#define WW   512
#define HWSZ (HH*WW)
#define KSEL 262          // int(512*512*0.001)

// ---------------- scratch (device globals; no allocation allowed) ----------------
__device__ float  g_guid [BB*HWSZ];
__device__ float  g_hmin1[BB*HWSZ];
__device__ float  g_dc1  [BB*HWSZ];
__device__ float  g_hmin2[BB*HWSZ];
__device__ float  g_p    [BB*HWSZ];
__device__ float4 g_b4h  [BB*HWSZ];
__device__ float2 g_ab   [BB*HWSZ];
__device__ float2 g_abh  [BB*HWSZ];

__device__ unsigned g_hist[BB*256];
__device__ unsigned g_prefix[BB];
__device__ int      g_rem[BB];
__device__ int      g_cntgt[BB];
__device__ int      g_ccount[BB];
__device__ unsigned g_cand[BB*HWSZ];
__device__ float    g_mapA[BB*3];
__device__ float    g_invAh[BB*3];

__device__ __forceinline__ float4 f4add(float4 a, float4 b){
    return make_float4(a.x+b.x, a.y+b.y, a.z+b.z, a.w+b.w);
}
__device__ __forceinline__ float4 f4sub(float4 a, float4 b){
    return make_float4(a.x-b.x, a.y-b.y, a.z-b.z, a.w-b.w);
}

// ---------------- init selection state ----------------
__global__ void k_init(){
    int t = blockIdx.x*blockDim.x + threadIdx.x;
    if (t < BB*256) g_hist[t] = 0;
    if (t < BB) { g_rem[t]=KSEL; g_cntgt[t]=0; g_prefix[t]=0; g_ccount[t]=0; }
}

// ---------------- stage 1: guidance + channel-min + horizontal min15 ----------------
__global__ void k_prep_minh(const float* __restrict__ x){
    int row = blockIdx.x, b = blockIdx.y, t = threadIdx.x;
    const float* xb = x + (size_t)b*3*HWSZ + (size_t)row*WW;
    float r = xb[t], g = xb[HWSZ+t], bl = xb[2*HWSZ+t];
    size_t o = (size_t)b*HWSZ + (size_t)row*WW;
    g_guid[o+t] = (0.2989f*r + 0.587f*g + 0.114f*bl + 1.0f)*0.5f;
    float ip0=(r+1.0f)*0.5f, ip1=(g+1.0f)*0.5f, ip2=(bl+1.0f)*0.5f;
    float mn = fminf(ip0, fminf(ip1, ip2));
    __shared__ float s[WW+14];
    s[t+7] = mn;
    if (t < 7){ s[t]=1.0f; s[t+WW+7]=1.0f; }
    __syncthreads();
    float m = s[t];
    #pragma unroll
    for (int i=1;i<15;i++) m = fminf(m, s[t+i]);
    g_hmin1[o+t] = m;
}

// ---------------- vertical min15 (MODE 0: ->dc1 ; MODE 1: -> trans_raw p) ----------------
template<int MODE>
__global__ void k_minv(){
    const float* src = MODE ? g_hmin2 : g_hmin1;
    float*       dst = MODE ? g_p     : g_dc1;
    int b  = blockIdx.z;
    int bx = blockIdx.x*32, by = blockIdx.y*128;
    int tx = threadIdx.x, ty = threadIdx.y;
    int tid = ty*32+tx;
    __shared__ float s[142][32];
    const float* sb = src + (size_t)b*HWSZ;
    for (int i=tid; i<142*32; i+=256){
        int rr = i>>5, cc = i&31;
        int gy = by - 7 + rr;
        s[rr][cc] = (gy>=0 && gy<HH) ? sb[(size_t)gy*WW + bx + cc] : 1.0f;
    }
    __syncthreads();
    float* db = dst + (size_t)b*HWSZ;
    #pragma unroll
    for (int o=0;o<16;o++){
        int ry = ty + o*8;
        float m = s[ry][tx];
        #pragma unroll
        for (int i=1;i<15;i++) m = fminf(m, s[ry+i][tx]);
        db[(size_t)(by+ry)*WW + bx + tx] = MODE ? (1.0f - 0.95f*m) : m;
    }
}

// ---------------- radix-select: 8-bit histogram pass ----------------
__global__ void k_hist(int shift){
    int b = blockIdx.y;
    __shared__ unsigned sh[256];
    int tid = threadIdx.x;
    sh[tid] = 0;
    __syncthreads();
    unsigned pref = g_prefix[b];
    const float* dc = g_dc1 + (size_t)b*HWSZ;
    for (int i = blockIdx.x*256 + tid; i < HWSZ; i += 64*256){
        unsigned bits = __float_as_uint(dc[i]);
        bool ok;
        if (shift == 24) ok = true;
        else ok = ((bits >> (shift+8)) == pref);
        if (ok){
            unsigned bin = (bits >> shift) & 255u;
            unsigned am = __activemask();
            unsigned mm = __match_any_sync(am, bin);
            int leader = __ffs(mm) - 1;
            if ((tid & 31) == leader) atomicAdd(&sh[bin], (unsigned)__popc(mm));
        }
    }
    __syncthreads();
    if (sh[tid]) atomicAdd(&g_hist[b*256+tid], sh[tid]);
}

__global__ void k_scan(){
    int b = threadIdx.x;
    if (b >= BB) return;
    unsigned* h = g_hist + b*256;
    int rem = g_rem[b];
    int cum = 0, chosen = 0;
    for (int bin=255; bin>=0; --bin){
        int c = (int)h[bin];
        if (cum + c >= rem){ chosen = bin; break; }
        cum += c;
    }
    g_prefix[b] = (g_prefix[b] << 8) | (unsigned)chosen;
    g_cntgt[b] += cum;
    g_rem[b]    = rem - cum;
    for (int j=0;j<256;j++) h[j]=0;
}

__global__ void k_collect(){
    int b = blockIdx.y;
    unsigned tau = g_prefix[b];
    const float* dc = g_dc1 + (size_t)b*HWSZ;
    for (int i = blockIdx.x*256 + threadIdx.x; i < HWSZ; i += 64*256){
        unsigned bits = __float_as_uint(dc[i]);
        if (bits >= tau){
            int pos = atomicAdd(&g_ccount[b], 1);
            g_cand[(size_t)b*HWSZ + pos] = (unsigned)i | (bits==tau ? 0x80000000u : 0u);
        }
    }
}

// ---------------- exact tie resolution + argmax intensity -> A ----------------
__global__ void k_select(const float* __restrict__ x){
    int b = blockIdx.x;
    int tid = threadIdx.x;
    int n = g_ccount[b];
    int m = g_rem[b];                     // how many of the ==tau group are selected
    const unsigned* cand = g_cand + (size_t)b*HWSZ;
    __shared__ int s_cnt;
    int lo=0, hi=HWSZ-1;
    while (lo < hi){
        int mid = (lo+hi) >> 1;
        if (tid==0) s_cnt = 0;
        __syncthreads();
        int local = 0;
        for (int j=tid; j<n; j+=256){
            unsigned e = cand[j];
            if (e & 0x80000000u){ int idx = (int)(e & 0x7fffffffu); if (idx <= mid) local++; }
        }
        if (local) atomicAdd(&s_cnt, local);
        __syncthreads();
        int c = s_cnt;
        __syncthreads();
        if (c >= m) hi = mid; else lo = mid+1;
    }
    int idx_cut = lo;

    float bi=-1e30f, bd=-1e30f; int bix = 0x7fffffff;
    const float* xb = x + (size_t)b*3*HWSZ;
    const float* dc = g_dc1 + (size_t)b*HWSZ;
    for (int j=tid; j<n; j+=256){
        unsigned e = cand[j];
        int idx = (int)(e & 0x7fffffffu);
        bool eq = (e & 0x80000000u) != 0;
        if (!eq || idx <= idx_cut){
            float r =(xb[idx]       +1.0f)*0.5f;
            float g =(xb[HWSZ+idx]  +1.0f)*0.5f;
            float bl=(xb[2*HWSZ+idx]+1.0f)*0.5f;
            float inten = 0.2989f*r + 0.587f*g + 0.114f*bl;
            float dv = dc[idx];
            bool better = (inten > bi) ||
                          (inten==bi && (dv > bd || (dv==bd && idx < bix)));
            if (better){ bi=inten; bd=dv; bix=idx; }
        }
    }
    __shared__ float sI[256], sD[256];
    __shared__ int   sX[256];
    sI[tid]=bi; sD[tid]=bd; sX[tid]=bix;
    __syncthreads();
    for (int s=128; s>0; s>>=1){
        if (tid < s){
            float oi=sI[tid+s], od=sD[tid+s]; int ox=sX[tid+s];
            bool better = (oi > sI[tid]) ||
                          (oi==sI[tid] && (od > sD[tid] || (od==sD[tid] && ox < sX[tid])));
            if (better){ sI[tid]=oi; sD[tid]=od; sX[tid]=ox; }
        }
        __syncthreads();
    }
    if (tid < 3){
        int idx = sX[0];
        float a  = (xb[(size_t)tid*HWSZ + idx] + 1.0f)*0.5f;
        float mA = a*2.0f - 1.0f;
        g_mapA[b*3+tid]  = mA;
        g_invAh[b*3+tid] = 1.0f / ((mA + 1.0f)*0.5f);
    }
}

// ---------------- ratio channel-min + horizontal min15 ----------------
__global__ void k_ratio_minh(const float* __restrict__ x){
    int row = blockIdx.x, b = blockIdx.y, t = threadIdx.x;
    const float* xb = x + (size_t)b*3*HWSZ + (size_t)row*WW;
    float inv0=g_invAh[b*3], inv1=g_invAh[b*3+1], inv2=g_invAh[b*3+2];
    float r =(xb[t]       +1.0f)*0.5f;
    float g =(xb[HWSZ+t]  +1.0f)*0.5f;
    float bl=(xb[2*HWSZ+t]+1.0f)*0.5f;
    float mn = fminf(r*inv0, fminf(g*inv1, bl*inv2));
    __shared__ float s[WW+14];
    s[t+7] = mn;
    if (t < 7){ s[t]=1.0f; s[t+WW+7]=1.0f; }
    __syncthreads();
    float m = s[t];
    #pragma unroll
    for (int i=1;i<15;i++) m = fminf(m, s[t+i]);
    g_hmin2[(size_t)b*HWSZ + (size_t)row*WW + t] = m;
}

// ---------------- guided filter: H box of (I,p,Ip,II) ----------------
__global__ void k_box4h(){
    int b   = blockIdx.z;
    int row = blockIdx.y*4 + threadIdx.y;
    int tx  = threadIdx.x;
    __shared__ float4 s[4][542];
    const float* Ib = g_guid + (size_t)b*HWSZ + (size_t)row*WW;
    const float* pb = g_p    + (size_t)b*HWSZ + (size_t)row*WW;
    for (int i=tx; i<542; i+=64){
        int c = i-15;
        float Iv=0.f, pv=0.f;
        if (c>=0 && c<WW){ Iv=Ib[c]; pv=pb[c]; }
        s[threadIdx.y][i] = make_float4(Iv, pv, Iv*pv, Iv*Iv);
    }
    __syncthreads();
    int c0 = tx*8;
    float4 acc = make_float4(0,0,0,0);
    #pragma unroll
    for (int i=0;i<31;i++) acc = f4add(acc, s[threadIdx.y][c0+i]);
    float4* dst = g_b4h + (size_t)b*HWSZ + (size_t)row*WW;
    dst[c0] = acc;
    #pragma unroll
    for (int j=1;j<8;j++){
        acc = f4add(acc, s[threadIdx.y][c0+30+j]);
        acc = f4sub(acc, s[threadIdx.y][c0+j-1]);
        dst[c0+j] = acc;
    }
}

// ---------------- guided filter: V box + a,b ----------------
__global__ void k_box4v_ab(){
    int b  = blockIdx.z;
    int bx = blockIdx.x*32, by = blockIdx.y*64;
    int tx = threadIdx.x, ty = threadIdx.y;
    int tid = ty*32+tx;
    __shared__ float4 s[94][32];
    const float4* sb = g_b4h + (size_t)b*HWSZ;
    for (int i=tid; i<94*32; i+=256){
        int rr=i>>5, cc=i&31;
        int gy = by-15+rr;
        s[rr][cc] = (gy>=0 && gy<HH) ? sb[(size_t)gy*WW+bx+cc] : make_float4(0,0,0,0);
    }
    __syncthreads();
    int gx = bx+tx;
    float fnx = (float)(min(gx+15,WW-1) - max(gx-15,0) + 1);
    int r0 = ty*8;
    float4 acc = make_float4(0,0,0,0);
    #pragma unroll
    for (int i=0;i<31;i++) acc = f4add(acc, s[r0+i][tx]);
    float2* db = g_ab + (size_t)b*HWSZ;
    #pragma unroll
    for (int j=0;j<8;j++){
        if (j>0){ acc = f4add(acc, s[r0+30+j][tx]); acc = f4sub(acc, s[r0+j-1][tx]); }
        int gy = by + r0 + j;
        float fny = (float)(min(gy+15,HH-1) - max(gy-15,0) + 1);
        float nInv = __frcp_rn(fnx*fny);
        float mI=acc.x*nInv, mp=acc.y*nInv, mIp=acc.z*nInv, mII=acc.w*nInv;
        float cov = mIp - mI*mp;
        float var = mII - mI*mI;
        float a   = cov / (var + 1e-3f);
        float bb2 = mp - a*mI;
        db[(size_t)gy*WW+gx] = make_float2(a, bb2);
    }
}

// ---------------- guided filter: H box of (a,b) ----------------
__global__ void k_abh(){
    int b   = blockIdx.z;
    int row = blockIdx.y*4 + threadIdx.y;
    int tx  = threadIdx.x;
    __shared__ float2 s[4][542];
    const float2* ab = g_ab + (size_t)b*HWSZ + (size_t)row*WW;
    for (int i=tx; i<542; i+=64){
        int c = i-15;
        s[threadIdx.y][i] = (c>=0 && c<WW) ? ab[c] : make_float2(0,0);
    }
    __syncthreads();
    int c0 = tx*8;
    float2 acc = make_float2(0,0);
    #pragma unroll
    for (int i=0;i<31;i++){ acc.x += s[threadIdx.y][c0+i].x; acc.y += s[threadIdx.y][c0+i].y; }
    float2* dst = g_abh + (size_t)b*HWSZ + (size_t)row*WW;
    dst[c0] = acc;
    #pragma unroll
    for (int j=1;j<8;j++){
        acc.x += s[threadIdx.y][c0+30+j].x; acc.y += s[threadIdx.y][c0+30+j].y;
        acc.x -= s[threadIdx.y][c0+j-1].x;  acc.y -= s[threadIdx.y][c0+j-1].y;
        dst[c0+j] = acc;
    }
}

// ---------------- guided filter: V box of (a,b) + T + J + A write ----------------
__global__ void k_abv_final(const float* __restrict__ x, float* __restrict__ out){
    int b  = blockIdx.z;
    int bx = blockIdx.x*32, by = blockIdx.y*64;
    int tx = threadIdx.x, ty = threadIdx.y;
    int tid = ty*32+tx;
    __shared__ float2 s[94][32];
    const float2* sb = g_abh + (size_t)b*HWSZ;
    for (int i=tid; i<94*32; i+=256){
        int rr=i>>5, cc=i&31;
        int gy = by-15+rr;
        s[rr][cc] = (gy>=0 && gy<HH) ? sb[(size_t)gy*WW+bx+cc] : make_float2(0,0);
    }
    __syncthreads();
    int gx = bx+tx;
    float fnx = (float)(min(gx+15,WW-1) - max(gx-15,0) + 1);
    float mA0=g_mapA[b*3], mA1=g_mapA[b*3+1], mA2=g_mapA[b*3+2];
    int r0 = ty*8;
    float2 acc = make_float2(0,0);
    #pragma unroll
    for (int i=0;i<31;i++){ acc.x += s[r0+i][tx].x; acc.y += s[r0+i][tx].y; }
    float* outJ = out;
    float* outT = out + (size_t)BB*3*HWSZ;
    float* outA = out + (size_t)BB*3*HWSZ + (size_t)BB*HWSZ;
    const float* xb = x + (size_t)b*3*HWSZ;
    #pragma unroll
    for (int j=0;j<8;j++){
        if (j>0){
            acc.x += s[r0+30+j][tx].x; acc.y += s[r0+30+j][tx].y;
            acc.x -= s[r0+j-1][tx].x;  acc.y -= s[r0+j-1][tx].y;
        }
        int gy = by + r0 + j;
        float fny = (float)(min(gy+15,HH-1) - max(gy-15,0) + 1);
        float nInv = __frcp_rn(fnx*fny);
        size_t idx = (size_t)gy*WW + gx;
        float I = g_guid[(size_t)b*HWSZ + idx];
        float T = (acc.x*nInv)*I + acc.y*nInv;
        outT[(size_t)b*HWSZ + idx] = T;
        float invT = 1.0f / T;
        float x0=xb[idx], x1=xb[HWSZ+idx], x2=xb[2*HWSZ+idx];
        size_t jb = (size_t)b*3*HWSZ + idx;
        outJ[jb]          = ((x0+1.0f)*0.5f - mA0)*invT + mA0;
        outJ[jb+HWSZ]     = ((x1+1.0f)*0.5f - mA1)*invT + mA1;
        outJ[jb+2*HWSZ]   = ((x2+1.0f)*0.5f - mA2)*invT + mA2;
        outA[jb]        = mA0;
        outA[jb+HWSZ]   = mA1;
        outA[jb+2*HWSZ] = mA2;
    }
}

// ---------------- launch ----------------
extern "C" void kernel_launch(void* const* d_in, const int* in_sizes, int n_in,
                              void* d_out, int out_size){
    (void)in_sizes; (void)n_in; (void)out_size;
    const float* x = (const float*)d_in[0];
    float* out = (float*)d_out;

    k_init<<<16,256>>>();
    k_prep_minh<<<dim3(HH,BB), WW>>>(x);
    k_minv<0><<<dim3(16,4,BB), dim3(32,8)>>>();

    k_hist<<<dim3(64,BB),256>>>(24); k_scan<<<1,BB>>>();
    k_hist<<<dim3(64,BB),256>>>(16); k_scan<<<1,BB>>>();
    k_hist<<<dim3(64,BB),256>>>(8);  k_scan<<<1,BB>>>();
    k_hist<<<dim3(64,BB),256>>>(0);  k_scan<<<1,BB>>>();
    k_collect<<<dim3(64,BB),256>>>();
    k_select<<<BB,256>>>(x);

    k_ratio_minh<<<dim3(HH,BB), WW>>>(x);
    k_minv<1><<<dim3(16,4,BB), dim3(32,8)>>>();

    k_box4h<<<dim3(1,HH/4,BB), dim3(64,4)>>>();
    k_box4v_ab<<<dim3(WW/32,HH/64,BB), dim3(32,8)>>>();
    k_abh<<<dim3(1,HH/4,BB), dim3(64,4)>>>();
    k_abv_final<<<dim3(WW/32,HH/64,BB), dim3(32,8)>>>(x, out);
}

// round 3
// speedup vs baseline: 1.6570x; 1.6570x over previous
#include <cuda_runtime.h>
#include <cstdint>

#define BB   16
#define HH   512
#define WW   512
#define HWSZ (HH*WW)
#define KSEL 262          // int(512*512*0.001)
#define NBIN 4096
#define CAP  65536

// ---------------- scratch (device globals; no allocation allowed) ----------------
__device__ float  g_guid [BB*HWSZ];
__device__ float  g_hmin1[BB*HWSZ];
__device__ float  g_dc1  [BB*HWSZ];
__device__ float  g_hmin2[BB*HWSZ];
__device__ float  g_p    [BB*HWSZ];
__device__ float4 g_b4h  [BB*HWSZ];
__device__ float2 g_ab   [BB*HWSZ];
__device__ float2 g_abh  [BB*HWSZ];

__device__ unsigned g_hist4k[BB*NBIN];
__device__ int      g_binlo[BB];
__device__ int      g_rem[BB];
__device__ int      g_ccount[BB];
__device__ unsigned long long g_cand[(size_t)BB*CAP];
__device__ float    g_mapA[BB*3];
__device__ float    g_invAh[BB*3];

__device__ __forceinline__ float4 f4add(float4 a, float4 b){
    return make_float4(a.x+b.x, a.y+b.y, a.z+b.z, a.w+b.w);
}

// ---------------- init selection state ----------------
__global__ void k_init(){
    int t = blockIdx.x*blockDim.x + threadIdx.x;
    if (t < BB*NBIN) g_hist4k[t] = 0;
    if (t < BB) g_ccount[t] = 0;
}

// ---------- stage 1: guidance + channel-min + horizontal min15 (float4) ----------
__global__ void k_prep_minh(const float* __restrict__ x){
    int row = blockIdx.x, b = blockIdx.y, t = threadIdx.x;  // t < 128
    const float4* xr = (const float4*)(x + (size_t)b*3*HWSZ + (size_t)row*WW);
    float4 r  = xr[t];
    float4 g  = xr[HWSZ/4 + t];
    float4 bl = xr[2*(HWSZ/4) + t];
    size_t o4 = ((size_t)b*HWSZ + (size_t)row*WW) >> 2;
    float4 gv;
    gv.x = (0.2989f*r.x + 0.587f*g.x + 0.114f*bl.x + 1.0f)*0.5f;
    gv.y = (0.2989f*r.y + 0.587f*g.y + 0.114f*bl.y + 1.0f)*0.5f;
    gv.z = (0.2989f*r.z + 0.587f*g.z + 0.114f*bl.z + 1.0f)*0.5f;
    gv.w = (0.2989f*r.w + 0.587f*g.w + 0.114f*bl.w + 1.0f)*0.5f;
    ((float4*)g_guid)[o4 + t] = gv;
    // min over channels of (v+1)/2 == (min over channels of v + 1)/2 (monotone, bit-safe)
    float4 mn;
    mn.x = (fminf(r.x, fminf(g.x, bl.x)) + 1.0f)*0.5f;
    mn.y = (fminf(r.y, fminf(g.y, bl.y)) + 1.0f)*0.5f;
    mn.z = (fminf(r.z, fminf(g.z, bl.z)) + 1.0f)*0.5f;
    mn.w = (fminf(r.w, fminf(g.w, bl.w)) + 1.0f)*0.5f;
    __shared__ float s[WW + 32];
    *(float4*)&s[16 + 4*t] = mn;
    if (t < 7){ s[9+t] = 1.0f; s[528+t] = 1.0f; }
    __syncthreads();
    const float* a = &s[4*t + 9];
    float c12 = a[3];
    #pragma unroll
    for (int j=4; j<=14; j++) c12 = fminf(c12, a[j]);
    float4 o;
    o.x = fminf(fminf(a[0], a[1]), fminf(a[2], c12));
    o.y = fminf(fminf(a[1], a[2]), fminf(c12, a[15]));
    o.z = fminf(a[2], fminf(c12, fminf(a[15], a[16])));
    o.w = fminf(c12, fminf(a[15], fminf(a[16], a[17])));
    ((float4*)g_hmin1)[o4 + t] = o;
}

// ---------- vertical min15 -> dc1 + fused 4096-bin histogram ----------
__global__ void k_minv0_hist(){
    int b  = blockIdx.z;
    int bx = blockIdx.x*32, by = blockIdx.y*128;
    int tx = threadIdx.x, ty = threadIdx.y;
    int tid = ty*32 + tx;
    __shared__ float s[142][32];
    __shared__ unsigned shh[NBIN];
    for (int i = tid; i < NBIN; i += 256) shh[i] = 0;
    const float* sb = g_hmin1 + (size_t)b*HWSZ;
    for (int i = tid; i < 142*8; i += 256){
        int rr = i >> 3, c4 = i & 7;
        int gy = by - 7 + rr;
        float4 v = (gy >= 0 && gy < HH)
                   ? ((const float4*)(sb + (size_t)gy*WW + bx))[c4]
                   : make_float4(1,1,1,1);
        *(float4*)&s[rr][c4*4] = v;
    }
    __syncthreads();
    float* db = g_dc1 + (size_t)b*HWSZ;
    #pragma unroll
    for (int o = 0; o < 16; o++){
        int ry = ty + o*8;
        float m = s[ry][tx];
        #pragma unroll
        for (int i = 1; i < 15; i++) m = fminf(m, s[ry+i][tx]);
        db[(size_t)(by+ry)*WW + bx + tx] = m;
        unsigned bin = min(4095u, (unsigned)(m * 16384.0f));
        unsigned mm = __match_any_sync(0xffffffffu, bin);
        if (tx == __ffs(mm)-1) atomicAdd(&shh[bin], (unsigned)__popc(mm));
    }
    __syncthreads();
    unsigned* gh = g_hist4k + b*NBIN;
    for (int i = tid; i < NBIN; i += 256)
        if (shh[i]) atomicAdd(&gh[i], shh[i]);
}

// ---------- scan histogram (one block per batch) ----------
__global__ void k_scan(){
    int b = blockIdx.x, t = threadIdx.x;
    const unsigned* h = g_hist4k + b*NBIN;
    __shared__ unsigned ps[256];
    __shared__ unsigned ex[257];
    int hi_bin = 4095 - t*16;
    unsigned v[16]; unsigned sum = 0;
    #pragma unroll
    for (int i = 0; i < 16; i++){ v[i] = h[hi_bin - i]; sum += v[i]; }
    ps[t] = sum;
    __syncthreads();
    if (t == 0){ ex[0] = 0; for (int i = 0; i < 256; i++) ex[i+1] = ex[i] + ps[i]; }
    __syncthreads();
    unsigned cum = ex[t];
    #pragma unroll
    for (int i = 0; i < 16; i++){
        unsigned c = v[i];
        if (cum < KSEL && cum + c >= KSEL){
            g_binlo[b] = hi_bin - i;
            g_rem[b]   = KSEL - (int)cum;   // slots to fill from boundary bin downward (by value)
        }
        cum += c;
    }
}

// ---------- collect candidates (bin >= binlo) ----------
__global__ void k_collect(){
    int b = blockIdx.y;
    int binlo = g_binlo[b];
    const float4* dc = (const float4*)(g_dc1 + (size_t)b*HWSZ);
    unsigned long long* cb = g_cand + (size_t)b*CAP;
    for (int i = blockIdx.x*256 + threadIdx.x; i < HWSZ/4; i += 64*256){
        float4 v = dc[i];
        float vv[4] = {v.x, v.y, v.z, v.w};
        #pragma unroll
        for (int k = 0; k < 4; k++){
            unsigned bin = min(4095u, (unsigned)(vv[k]*16384.0f));
            if ((int)bin >= binlo){
                int pos = atomicAdd(&g_ccount[b], 1);
                if (pos < CAP)
                    cb[pos] = ((unsigned long long)__float_as_uint(vv[k]) << 32) | (unsigned)(i*4 + k);
            }
        }
    }
}

// ---------- exact select over candidates: radix for tau, tie cut, argmax ----------
__global__ void k_select(const float* __restrict__ x){
    int b = blockIdx.x, tid = threadIdx.x;
    int n = min(g_ccount[b], CAP);
    const unsigned long long* cand = g_cand + (size_t)b*CAP;

    __shared__ unsigned hist[256];
    __shared__ unsigned s_pref;
    __shared__ int s_rem;
    if (tid == 0){ s_pref = 0; s_rem = KSEL; }
    __syncthreads();
    for (int shift = 24; shift >= 0; shift -= 8){
        hist[tid] = 0;
        __syncthreads();
        unsigned pref = s_pref;
        for (int j = tid; j < n; j += 256){
            unsigned bits = (unsigned)(cand[j] >> 32);
            if (shift == 24 || (bits >> (shift+8)) == pref)
                atomicAdd(&hist[(bits >> shift) & 255u], 1u);
        }
        __syncthreads();
        if (tid == 0){
            int rem = s_rem, cum = 0, chosen = 0;
            for (int bin = 255; bin >= 0; --bin){
                int c = (int)hist[bin];
                if (cum + c >= rem){ chosen = bin; break; }
                cum += c;
            }
            s_pref = (pref << 8) | (unsigned)chosen;
            s_rem  = rem - cum;
        }
        __syncthreads();
    }
    unsigned tau = s_pref;
    int m = s_rem;                         // selected count within value==tau group

    // idx_cut = m-th smallest index among value==tau (top_k ties: lower index first)
    __shared__ int s_cnt;
    int lo = 0, hi = HWSZ - 1;
    while (lo < hi){
        int mid = (lo + hi) >> 1;
        if (tid == 0) s_cnt = 0;
        __syncthreads();
        int local = 0;
        for (int j = tid; j < n; j += 256){
            unsigned long long e = cand[j];
            if ((unsigned)(e >> 32) == tau && (int)(e & 0xffffffffu) <= mid) local++;
        }
        if (local) atomicAdd(&s_cnt, local);
        __syncthreads();
        int c = s_cnt;
        __syncthreads();
        if (c >= m) hi = mid; else lo = mid + 1;
    }
    int idx_cut = lo;

    // argmax intensity, tie-break by top_k order (value desc, index asc)
    float bi = -1e30f, bd = -1e30f; int bix = 0x7fffffff;
    const float* xb = x + (size_t)b*3*HWSZ;
    for (int j = tid; j < n; j += 256){
        unsigned long long e = cand[j];
        unsigned bits = (unsigned)(e >> 32);
        int idx = (int)(e & 0xffffffffu);
        if (bits > tau || (bits == tau && idx <= idx_cut)){
            float r  = (xb[idx]        + 1.0f)*0.5f;
            float g  = (xb[HWSZ+idx]   + 1.0f)*0.5f;
            float bl = (xb[2*HWSZ+idx] + 1.0f)*0.5f;
            float inten = 0.2989f*r + 0.587f*g + 0.114f*bl;
            float dv = __uint_as_float(bits);
            bool better = (inten > bi) ||
                          (inten == bi && (dv > bd || (dv == bd && idx < bix)));
            if (better){ bi = inten; bd = dv; bix = idx; }
        }
    }
    __shared__ float sI[256], sD[256];
    __shared__ int   sX[256];
    sI[tid] = bi; sD[tid] = bd; sX[tid] = bix;
    __syncthreads();
    for (int s = 128; s > 0; s >>= 1){
        if (tid < s){
            float oi = sI[tid+s], od = sD[tid+s]; int ox = sX[tid+s];
            bool better = (oi > sI[tid]) ||
                          (oi == sI[tid] && (od > sD[tid] || (od == sD[tid] && ox < sX[tid])));
            if (better){ sI[tid] = oi; sD[tid] = od; sX[tid] = ox; }
        }
        __syncthreads();
    }
    if (tid < 3){
        int idx = sX[0];
        float a  = (xb[(size_t)tid*HWSZ + idx] + 1.0f)*0.5f;
        float mA = a*2.0f - 1.0f;
        g_mapA[b*3+tid]  = mA;
        g_invAh[b*3+tid] = 1.0f / ((mA + 1.0f)*0.5f);
    }
}

// ---------- ratio channel-min + horizontal min15 (float4) ----------
__global__ void k_ratio_minh(const float* __restrict__ x){
    int row = blockIdx.x, b = blockIdx.y, t = threadIdx.x;  // t < 128
    const float4* xr = (const float4*)(x + (size_t)b*3*HWSZ + (size_t)row*WW);
    float inv0 = g_invAh[b*3], inv1 = g_invAh[b*3+1], inv2 = g_invAh[b*3+2];
    float4 r  = xr[t];
    float4 g  = xr[HWSZ/4 + t];
    float4 bl = xr[2*(HWSZ/4) + t];
    float4 mn;
    mn.x = fminf((r.x+1.0f)*0.5f*inv0, fminf((g.x+1.0f)*0.5f*inv1, (bl.x+1.0f)*0.5f*inv2));
    mn.y = fminf((r.y+1.0f)*0.5f*inv0, fminf((g.y+1.0f)*0.5f*inv1, (bl.y+1.0f)*0.5f*inv2));
    mn.z = fminf((r.z+1.0f)*0.5f*inv0, fminf((g.z+1.0f)*0.5f*inv1, (bl.z+1.0f)*0.5f*inv2));
    mn.w = fminf((r.w+1.0f)*0.5f*inv0, fminf((g.w+1.0f)*0.5f*inv1, (bl.w+1.0f)*0.5f*inv2));
    __shared__ float s[WW + 32];
    *(float4*)&s[16 + 4*t] = mn;
    if (t < 7){ s[9+t] = 1.0f; s[528+t] = 1.0f; }
    __syncthreads();
    const float* a = &s[4*t + 9];
    float c12 = a[3];
    #pragma unroll
    for (int j=4; j<=14; j++) c12 = fminf(c12, a[j]);
    float4 o;
    o.x = fminf(fminf(a[0], a[1]), fminf(a[2], c12));
    o.y = fminf(fminf(a[1], a[2]), fminf(c12, a[15]));
    o.z = fminf(a[2], fminf(c12, fminf(a[15], a[16])));
    o.w = fminf(c12, fminf(a[15], fminf(a[16], a[17])));
    ((float4*)g_hmin2)[(((size_t)b*HWSZ + (size_t)row*WW) >> 2) + t] = o;
}

// ---------- vertical min15 -> trans_raw p ----------
__global__ void k_minv1(){
    int b  = blockIdx.z;
    int bx = blockIdx.x*32, by = blockIdx.y*128;
    int tx = threadIdx.x, ty = threadIdx.y;
    int tid = ty*32 + tx;
    __shared__ float s[142][32];
    const float* sb = g_hmin2 + (size_t)b*HWSZ;
    for (int i = tid; i < 142*8; i += 256){
        int rr = i >> 3, c4 = i & 7;
        int gy = by - 7 + rr;
        float4 v = (gy >= 0 && gy < HH)
                   ? ((const float4*)(sb + (size_t)gy*WW + bx))[c4]
                   : make_float4(1,1,1,1);
        *(float4*)&s[rr][c4*4] = v;
    }
    __syncthreads();
    float* db = g_p + (size_t)b*HWSZ;
    #pragma unroll
    for (int o = 0; o < 16; o++){
        int ry = ty + o*8;
        float m = s[ry][tx];
        #pragma unroll
        for (int i = 1; i < 15; i++) m = fminf(m, s[ry+i][tx]);
        db[(size_t)(by+ry)*WW + bx + tx] = 1.0f - 0.95f*m;
    }
}

// ---------- guided filter: H box of (I,p,Ip,II), staged coalesced output ----------
// 2 rows/block to stay under the 48KB static smem limit.
__global__ void k_box4h(){
    int b    = blockIdx.z;
    int row0 = blockIdx.y*2;
    int tx = threadIdx.x, ty = threadIdx.y;   // (64,2)
    int tid = ty*64 + tx;
    __shared__ float sI[2][544], sp[2][544];
    __shared__ float4 so[2][512];
    const float4* I4 = (const float4*)(g_guid + (size_t)b*HWSZ + (size_t)(row0+ty)*WW);
    const float4* p4 = (const float4*)(g_p    + (size_t)b*HWSZ + (size_t)(row0+ty)*WW);
    for (int i = tx; i < 128; i += 64){
        *(float4*)&sI[ty][16 + 4*i] = I4[i];
        *(float4*)&sp[ty][16 + 4*i] = p4[i];
    }
    if (tx < 16){
        sI[ty][tx] = 0.f; sp[ty][tx] = 0.f;
        sI[ty][528+tx] = 0.f; sp[ty][528+tx] = 0.f;
    }
    __syncthreads();
    int c0 = tx*8;
    float4 acc = make_float4(0,0,0,0);
    #pragma unroll
    for (int i = 0; i < 31; i++){
        float Iv = sI[ty][c0+1+i], pv = sp[ty][c0+1+i];
        acc.x += Iv; acc.y += pv; acc.z += Iv*pv; acc.w += Iv*Iv;
    }
    so[ty][c0] = acc;
    #pragma unroll
    for (int j = 1; j < 8; j++){
        float Ia = sI[ty][c0+31+j], pa = sp[ty][c0+31+j];
        float Is = sI[ty][c0+j],    ps = sp[ty][c0+j];
        acc.x += Ia - Is; acc.y += pa - ps;
        acc.z += Ia*pa - Is*ps; acc.w += Ia*Ia - Is*Is;
        so[ty][c0+j] = acc;
    }
    __syncthreads();
    float4* dst = g_b4h + (size_t)b*HWSZ + (size_t)row0*WW;
    for (int i = tid; i < 1024; i += 128)
        dst[(size_t)(i>>9)*WW + (i & 511)] = so[i>>9][i & 511];
}

// ---------- guided filter: V box + a,b ----------
__global__ void k_box4v_ab(){
    int b  = blockIdx.z;
    int bx = blockIdx.x*32, by = blockIdx.y*64;
    int tx = threadIdx.x, ty = threadIdx.y;
    int tid = ty*32 + tx;
    __shared__ float4 s[94][32];
    const float4* sb = g_b4h + (size_t)b*HWSZ;
    for (int i = tid; i < 94*32; i += 256){
        int rr = i >> 5, cc = i & 31;
        int gy = by - 15 + rr;
        s[rr][cc] = (gy >= 0 && gy < HH) ? sb[(size_t)gy*WW + bx + cc] : make_float4(0,0,0,0);
    }
    __syncthreads();
    int gx = bx + tx;
    float fnx = (float)(min(gx+15, WW-1) - max(gx-15, 0) + 1);
    int r0 = ty*8;
    float4 acc = make_float4(0,0,0,0);
    #pragma unroll
    for (int i = 0; i < 31; i++) acc = f4add(acc, s[r0+i][tx]);
    float2* db = g_ab + (size_t)b*HWSZ;
    #pragma unroll
    for (int j = 0; j < 8; j++){
        if (j > 0){
            float4 va = s[r0+30+j][tx], vs = s[r0+j-1][tx];
            acc.x += va.x - vs.x; acc.y += va.y - vs.y;
            acc.z += va.z - vs.z; acc.w += va.w - vs.w;
        }
        int gy = by + r0 + j;
        float fny = (float)(min(gy+15, HH-1) - max(gy-15, 0) + 1);
        float nInv = __frcp_rn(fnx*fny);
        float mI = acc.x*nInv, mp = acc.y*nInv, mIp = acc.z*nInv, mII = acc.w*nInv;
        float cov = mIp - mI*mp;
        float var = mII - mI*mI;
        float a   = cov / (var + 1e-3f);
        float bb2 = mp - a*mI;
        db[(size_t)gy*WW + gx] = make_float2(a, bb2);
    }
}

// ---------- guided filter: H box of (a,b), staged coalesced output ----------
__global__ void k_abh(){
    int b    = blockIdx.z;
    int row0 = blockIdx.y*4;
    int tx = threadIdx.x, ty = threadIdx.y;  // (64,4)
    int tid = ty*64 + tx;
    __shared__ float sa[4][544], sb2[4][544];
    __shared__ float2 so[4][512];
    const float4* ab4 = (const float4*)(g_ab + (size_t)b*HWSZ + (size_t)(row0+ty)*WW);
    for (int i = tx; i < 256; i += 64){
        float4 v = ab4[i];
        sa [ty][16 + 2*i]   = v.x; sb2[ty][16 + 2*i]   = v.y;
        sa [ty][17 + 2*i]   = v.z; sb2[ty][17 + 2*i]   = v.w;
    }
    if (tx < 16){
        sa[ty][tx] = 0.f; sb2[ty][tx] = 0.f;
        sa[ty][528+tx] = 0.f; sb2[ty][528+tx] = 0.f;
    }
    __syncthreads();
    int c0 = tx*8;
    float2 acc = make_float2(0,0);
    #pragma unroll
    for (int i = 0; i < 31; i++){ acc.x += sa[ty][c0+1+i]; acc.y += sb2[ty][c0+1+i]; }
    so[ty][c0] = acc;
    #pragma unroll
    for (int j = 1; j < 8; j++){
        acc.x += sa [ty][c0+31+j] - sa [ty][c0+j];
        acc.y += sb2[ty][c0+31+j] - sb2[ty][c0+j];
        so[ty][c0+j] = acc;
    }
    __syncthreads();
    float2* dst = g_abh + (size_t)b*HWSZ + (size_t)row0*WW;
    const float4* sof = (const float4*)so;
    for (int i = tid; i < 1024; i += 256){
        int rr = i >> 8, cc = i & 255;
        ((float4*)(dst + (size_t)rr*WW))[cc] = sof[i];
    }
}

// ---------- guided filter: V box of (a,b) + T + J + A write ----------
__global__ void k_abv_final(const float* __restrict__ x, float* __restrict__ out){
    int b  = blockIdx.z;
    int bx = blockIdx.x*32, by = blockIdx.y*64;
    int tx = threadIdx.x, ty = threadIdx.y;
    int tid = ty*32 + tx;
    __shared__ float2 s[94][32];
    const float2* sb = g_abh + (size_t)b*HWSZ;
    for (int i = tid; i < 94*16; i += 256){
        int rr = i >> 4, c2 = (i & 15)*2;
        int gy = by - 15 + rr;
        float4 v = (gy >= 0 && gy < HH)
                   ? ((const float4*)(sb + (size_t)gy*WW + bx))[i & 15]
                   : make_float4(0,0,0,0);
        s[rr][c2]   = make_float2(v.x, v.y);
        s[rr][c2+1] = make_float2(v.z, v.w);
    }
    __syncthreads();
    int gx = bx + tx;
    float fnx = (float)(min(gx+15, WW-1) - max(gx-15, 0) + 1);
    float mA0 = g_mapA[b*3], mA1 = g_mapA[b*3+1], mA2 = g_mapA[b*3+2];
    int r0 = ty*8;
    float2 acc = make_float2(0,0);
    #pragma unroll
    for (int i = 0; i < 31; i++){ acc.x += s[r0+i][tx].x; acc.y += s[r0+i][tx].y; }
    float* outJ = out;
    float* outT = out + (size_t)BB*3*HWSZ;
    float* outA = out + (size_t)BB*3*HWSZ + (size_t)BB*HWSZ;
    const float* xb = x + (size_t)b*3*HWSZ;
    #pragma unroll
    for (int j = 0; j < 8; j++){
        if (j > 0){
            acc.x += s[r0+30+j][tx].x - s[r0+j-1][tx].x;
            acc.y += s[r0+30+j][tx].y - s[r0+j-1][tx].y;
        }
        int gy = by + r0 + j;
        float fny = (float)(min(gy+15, HH-1) - max(gy-15, 0) + 1);
        float nInv = __frcp_rn(fnx*fny);
        size_t idx = (size_t)gy*WW + gx;
        float I = g_guid[(size_t)b*HWSZ + idx];
        float T = (acc.x*nInv)*I + acc.y*nInv;
        outT[(size_t)b*HWSZ + idx] = T;
        float invT = 1.0f / T;
        float x0 = xb[idx], x1 = xb[HWSZ+idx], x2 = xb[2*HWSZ+idx];
        size_t jb = (size_t)b*3*HWSZ + idx;
        outJ[jb]          = ((x0+1.0f)*0.5f - mA0)*invT + mA0;
        outJ[jb+HWSZ]     = ((x1+1.0f)*0.5f - mA1)*invT + mA1;
        outJ[jb+2*HWSZ]   = ((x2+1.0f)*0.5f - mA2)*invT + mA2;
        outA[jb]          = mA0;
        outA[jb+HWSZ]     = mA1;
        outA[jb+2*HWSZ]   = mA2;
    }
}

// ---------------- launch ----------------
extern "C" void kernel_launch(void* const* d_in, const int* in_sizes, int n_in,
                              void* d_out, int out_size){
    (void)in_sizes; (void)n_in; (void)out_size;
    const float* x = (const float*)d_in[0];
    float* out = (float*)d_out;

    k_init<<<256, 256>>>();
    k_prep_minh<<<dim3(HH, BB), 128>>>(x);
    k_minv0_hist<<<dim3(16, 4, BB), dim3(32, 8)>>>();
    k_scan<<<BB, 256>>>();
    k_collect<<<dim3(64, BB), 256>>>();
    k_select<<<BB, 256>>>(x);

    k_ratio_minh<<<dim3(HH, BB), 128>>>(x);
    k_minv1<<<dim3(16, 4, BB), dim3(32, 8)>>>();

    k_box4h<<<dim3(1, HH/2, BB), dim3(64, 2)>>>();
    k_box4v_ab<<<dim3(WW/32, HH/64, BB), dim3(32, 8)>>>();
    k_abh<<<dim3(1, HH/4, BB), dim3(64, 4)>>>();
    k_abv_final<<<dim3(WW/32, HH/64, BB), dim3(32, 8)>>>(x, out);
}